// round 5
// baseline (speedup 1.0000x reference)
#include <cuda_runtime.h>
#include <math.h>

// ---------------- problem constants ----------------
#define NIMG 4
#define BATCH 8
#define SEQ 576
#define DIM 256
#define NHEAD 8
#define DHEAD 32
#define NLAYER 6
#define MLPDIM 512
#define NB (NIMG*BATCH)      // 32
#define TOK (NB*SEQ)         // 18432
#define KPATCH 768           // 3*16*16
#define GRID24 24

// ---------------- scratch (device globals; no allocation allowed) ----------------
// interleaved {tf32_hi, tf32_lo} pairs (u32 each)
__device__ unsigned g_im2[(long)NIMG*BATCH*SEQ*KPATCH*2];  // 113 MB
__device__ unsigned g_pe2[(long)TOK*DIM*2];                // 37.7 MB
__device__ unsigned g_q2 [(long)TOK*DIM*2];                // 37.7 MB (Q*scale, split)
__device__ unsigned g_o2 [(long)TOK*DIM*2];                // 37.7 MB
__device__ unsigned g_kvt[(long)TOK*512];                  // 37.7 MB (K|V tf32)
__device__ float    g_pe [(long)TOK*DIM];                  // 18.9 MB (f32, final feat)
__device__ unsigned g_cw2[(long)NIMG*DIM*KPATCH*2];
__device__ unsigned g_iw2[(long)NLAYER*3*DIM*DIM*2];
__device__ unsigned g_ow2[(long)NLAYER*DIM*DIM*2];
__device__ float    g_feat[BATCH*NIMG*DIM];

// ---------------- tf32 helpers ----------------
__device__ __forceinline__ unsigned f2tf(float f) {
    unsigned u; asm("cvt.rna.tf32.f32 %0, %1;" : "=r"(u) : "f"(f)); return u;
}
__device__ __forceinline__ void mma_tf32(float* d, const unsigned* a, unsigned b0, unsigned b1) {
    asm volatile(
        "mma.sync.aligned.m16n8k8.row.col.f32.tf32.tf32.f32 "
        "{%0,%1,%2,%3},{%4,%5,%6,%7},{%8,%9},{%0,%1,%2,%3};"
        : "+f"(d[0]), "+f"(d[1]), "+f"(d[2]), "+f"(d[3])
        : "r"(a[0]), "r"(a[1]), "r"(a[2]), "r"(a[3]), "r"(b0), "r"(b1));
}

// ---------------- weight split kernel ----------------
__global__ void cvt_k(const float* __restrict__ s, unsigned* __restrict__ d2, int n) {
    int i = blockIdx.x*256 + threadIdx.x;
    if (i >= n) return;
    float v = s[i];
    unsigned h = f2tf(v);
    uint2 p; p.x = h; p.y = f2tf(v - __uint_as_float(h));
    *(uint2*)&d2[(long)i*2] = p;
}

// ---------------- im2col (writes split pairs) ----------------
__global__ void im2col_k(const float* __restrict__ x) {
    long idx = (long)blockIdx.x*256 + threadIdx.x;
    const long total = (long)NIMG*BATCH*SEQ*KPATCH;
    if (idx >= total) return;
    int k   = (int)(idx % KPATCH);
    long r  = idx / KPATCH;
    int s   = (int)(r % SEQ);
    int b   = (int)((r / SEQ) % BATCH);
    int ni  = (int)(r / ((long)SEQ*BATCH));
    int c   = k >> 8;
    int py  = (k >> 4) & 15;
    int px  = k & 15;
    int gy  = s / GRID24, gx = s % GRID24;
    float v = x[(((long)b*12 + ni*3 + c)*384 + gy*16 + py)*384 + gx*16 + px];
    unsigned h = f2tf(v);
    uint2 p; p.x = h; p.y = f2tf(v - __uint_as_float(h));
    *(uint2*)&g_im2[idx*2] = p;
}

// ---------------- 3xTF32 GEMM from pre-split inputs ----------------
// C[M,N] = A[M,K] @ Bw[N,K]^T (+bias)(+pos). A2/B2 are {hi,lo}-interleaved u32.
// mode 0: write C f32 (if non-null) + C2 split pairs (row stride 2N).
// mode 1 (qkv): n<256 -> C2 = q2 (scaled, [m][512]); n>=256 -> kvt tf32 [m][512].
__global__ __launch_bounds__(256) void gemm3x(
    const unsigned* __restrict__ A2, const unsigned* __restrict__ B2,
    float* __restrict__ C, unsigned* __restrict__ C2, unsigned* __restrict__ kvt,
    int M, int N, int K,
    const float* __restrict__ bias, const float* __restrict__ pos,
    long strideA2, long strideB2, long strideC, int strideBias, int mode)
{
    A2 += (long)blockIdx.z * strideA2;
    B2 += (long)blockIdx.z * strideB2;
    if (C)  C  += (long)blockIdx.z * strideC;
    C2 += (long)blockIdx.z * strideC * 2;
    if (bias) bias += (long)blockIdx.z * strideBias;

    __shared__ unsigned As2[64][40];
    __shared__ unsigned Bs2[64][40];

    const int tid  = threadIdx.x;
    const int lane = tid & 31;
    const int w    = tid >> 5;
    const int r4   = lane >> 2;
    const int c4   = lane & 3;
    const int wm   = w & 3, wn = w >> 2;
    const int m0   = blockIdx.y * 64, n0 = blockIdx.x * 64;
    const int lrow = tid >> 2;
    const int lc8  = (tid & 3) * 8;

    float acc[4][4] = {};

    for (int k0 = 0; k0 < K; k0 += 16) {
        const unsigned* ap = &A2[(long)(m0+lrow)*2*K + 2*k0 + lc8];
        const unsigned* bp = &B2[(long)(n0+lrow)*2*K + 2*k0 + lc8];
        uint4 av0 = *(const uint4*)ap, av1 = *(const uint4*)(ap+4);
        uint4 bv0 = *(const uint4*)bp, bv1 = *(const uint4*)(bp+4);
        *(uint4*)&As2[lrow][lc8]   = av0; *(uint4*)&As2[lrow][lc8+4] = av1;
        *(uint4*)&Bs2[lrow][lc8]   = bv0; *(uint4*)&Bs2[lrow][lc8+4] = bv1;
        __syncthreads();
        #pragma unroll
        for (int kk = 0; kk < 2; kk++) {
            int kb = kk*8;
            uint2 af0 = *(const uint2*)&As2[wm*16+r4  ][(kb+c4)*2];
            uint2 af1 = *(const uint2*)&As2[wm*16+r4+8][(kb+c4)*2];
            uint2 af2 = *(const uint2*)&As2[wm*16+r4  ][(kb+c4+4)*2];
            uint2 af3 = *(const uint2*)&As2[wm*16+r4+8][(kb+c4+4)*2];
            unsigned ah[4] = {af0.x, af1.x, af2.x, af3.x};
            unsigned al[4] = {af0.y, af1.y, af2.y, af3.y};
            #pragma unroll
            for (int nt = 0; nt < 4; nt++) {
                uint2 bf0 = *(const uint2*)&Bs2[wn*32+nt*8+r4][(kb+c4)*2];
                uint2 bf1 = *(const uint2*)&Bs2[wn*32+nt*8+r4][(kb+c4+4)*2];
                mma_tf32(acc[nt], ah, bf0.x, bf1.x);
                mma_tf32(acc[nt], al, bf0.x, bf1.x);
                mma_tf32(acc[nt], ah, bf0.y, bf1.y);
            }
        }
        __syncthreads();
    }

    const float SCq = 0.17677669529663687f;   // 1/sqrt(32)
    #pragma unroll
    for (int nt = 0; nt < 4; nt++) {
        int n = n0 + wn*32 + nt*8 + c4*2;
        float bx = 0.f, by = 0.f;
        if (bias) { bx = bias[n]; by = bias[n+1]; }
        int row0 = m0 + wm*16 + r4, row1 = row0 + 8;
        float v00 = acc[nt][0]+bx, v01 = acc[nt][1]+by;
        float v10 = acc[nt][2]+bx, v11 = acc[nt][3]+by;
        if (mode == 1) {
            if (n < DIM) {
                v00 *= SCq; v01 *= SCq; v10 *= SCq; v11 *= SCq;
                unsigned h00=f2tf(v00), h01=f2tf(v01), h10=f2tf(v10), h11=f2tf(v11);
                uint4 p0 = make_uint4(h00, f2tf(v00-__uint_as_float(h00)),
                                      h01, f2tf(v01-__uint_as_float(h01)));
                uint4 p1 = make_uint4(h10, f2tf(v10-__uint_as_float(h10)),
                                      h11, f2tf(v11-__uint_as_float(h11)));
                *(uint4*)&C2[(long)row0*512 + n*2] = p0;
                *(uint4*)&C2[(long)row1*512 + n*2] = p1;
            } else {
                int nn = n - DIM;
                uint2 kv0; kv0.x = f2tf(v00); kv0.y = f2tf(v01);
                uint2 kv1; kv1.x = f2tf(v10); kv1.y = f2tf(v11);
                *(uint2*)&kvt[(long)row0*512 + nn] = kv0;
                *(uint2*)&kvt[(long)row1*512 + nn] = kv1;
            }
        } else {
            if (pos) {
                const float* p0 = pos + (long)(row0 % SEQ)*DIM + n;
                const float* p1 = pos + (long)(row1 % SEQ)*DIM + n;
                v00 += p0[0]; v01 += p0[1]; v10 += p1[0]; v11 += p1[1];
            }
            if (C) {
                *(float2*)&C[(long)row0*N + n] = make_float2(v00, v01);
                *(float2*)&C[(long)row1*N + n] = make_float2(v10, v11);
            }
            unsigned h00=f2tf(v00), h01=f2tf(v01), h10=f2tf(v10), h11=f2tf(v11);
            uint4 p0 = make_uint4(h00, f2tf(v00-__uint_as_float(h00)),
                                  h01, f2tf(v01-__uint_as_float(h01)));
            uint4 p1 = make_uint4(h10, f2tf(v10-__uint_as_float(h10)),
                                  h11, f2tf(v11-__uint_as_float(h11)));
            *(uint4*)&C2[(long)row0*2*N + n*2] = p0;
            *(uint4*)&C2[(long)row1*2*N + n*2] = p1;
        }
    }
}

// ---------------- fused attention (tf32 mma, pre-converted inputs) ----------------
#define KT_STR 580
#define SSTR 580
#define ATTN_FLOATS (32*KT_STR + 16*SSTR + 128 + 128 + 16 + 16 + 16)
#define ATTN_SMEM (ATTN_FLOATS*4)   // 112,576 B -> 2 CTA/SM

__global__ __launch_bounds__(256, 2) void attn_mma(
    float* __restrict__ attn_out, int layer)
{
    extern __shared__ float sm[];
    unsigned* Kt   = (unsigned*)sm;             // [32 dh][580 key] tf32 K^T; V^T overlay
    float* Ss      = sm + 32*KT_STR;            // [16 q][580 key] E (tf32-valued)
    float* pbufA   = Ss + 16*SSTR;              // [16][8]
    float* pbufB   = pbufA + 128;               // [16][8]
    float* rowmax  = pbufB + 128;               // [16]
    float* rinv0   = rowmax + 16;               // 1/sum(exact e)
    float* rinv1   = rinv0 + 16;                // 1/sum(rounded e)

    const int tid  = threadIdx.x;
    const int lane = tid & 31;
    const int w    = tid >> 5;
    const int r4   = lane >> 2;
    const int c4   = lane & 3;
    const int qt   = blockIdx.x;                // 0..35
    const int nb   = blockIdx.y;                // 0..31
    const unsigned* kvbase = g_kvt + (long)nb*SEQ*512;
    const long qrow = (long)(nb*SEQ + qt*16 + r4);

    float am[9][4];
    #pragma unroll
    for (int nt = 0; nt < 9; nt++)
        #pragma unroll
        for (int i = 0; i < 4; i++) am[nt][i] = 0.f;

    for (int h = 0; h < NHEAD; h++) {
        __syncthreads();                        // S0
        // ---- P1: load K^T [32 dh][576 keys] (already tf32) ----
        #pragma unroll 2
        for (int it = 0; it < 18; it++) {
            int key4 = (w + it*8)*4;
            const unsigned* kp = kvbase + (long)key4*512 + h*32 + lane;
            uint4 pk;
            pk.x = kp[0]; pk.y = kp[512]; pk.z = kp[1024]; pk.w = kp[1536];
            *(uint4*)&Kt[lane*KT_STR + key4] = pk;
        }
        __syncthreads();                        // S1

        // ---- P2: S = Q K^T, Q hi/lo pre-split; warp w -> keys [w*72,+72) ----
        float acc[9][4];
        #pragma unroll
        for (int nt = 0; nt < 9; nt++)
            #pragma unroll
            for (int i = 0; i < 4; i++) acc[nt][i] = 0.f;

        #pragma unroll
        for (int kc = 0; kc < 4; kc++) {
            unsigned ah[4], al[4];
            {
                const unsigned* qp = g_q2 + qrow*512 + (h*32 + kc*8 + c4)*2;
                uint2 qa = *(const uint2*)qp;
                uint2 qb = *(const uint2*)(qp + 8*512);
                uint2 qc = *(const uint2*)(qp + 8);
                uint2 qd = *(const uint2*)(qp + 8*512 + 8);
                ah[0]=qa.x; ah[1]=qb.x; ah[2]=qc.x; ah[3]=qd.x;
                al[0]=qa.y; al[1]=qb.y; al[2]=qc.y; al[3]=qd.y;
            }
            const unsigned* kb  = &Kt[(kc*8 + c4)*KT_STR + w*72 + r4];
            const unsigned* kb4 = kb + 4*KT_STR;
            #pragma unroll
            for (int nt = 0; nt < 9; nt++) {
                unsigned b0 = kb[nt*8], b1 = kb4[nt*8];
                mma_tf32(acc[nt], ah, b0, b1);
                mma_tf32(acc[nt], al, b0, b1);
            }
        }
        // partial row max
        {
            float pm[2] = {-1e30f, -1e30f};
            #pragma unroll
            for (int nt = 0; nt < 9; nt++) {
                pm[0] = fmaxf(pm[0], fmaxf(acc[nt][0], acc[nt][1]));
                pm[1] = fmaxf(pm[1], fmaxf(acc[nt][2], acc[nt][3]));
            }
            #pragma unroll
            for (int s = 0; s < 2; s++) {
                pm[s] = fmaxf(pm[s], __shfl_xor_sync(0xffffffffu, pm[s], 1));
                pm[s] = fmaxf(pm[s], __shfl_xor_sync(0xffffffffu, pm[s], 2));
            }
            if (c4 == 0) {
                pbufA[r4*8 + w]     = pm[0];
                pbufA[(r4+8)*8 + w] = pm[1];
            }
        }
        __syncthreads();                        // S2
        // ---- P3: rowmax reduce + load V^T (overwrites Kt) ----
        if (tid < 16) {
            float m = pbufA[tid*8];
            #pragma unroll
            for (int i = 1; i < 8; i++) m = fmaxf(m, pbufA[tid*8 + i]);
            rowmax[tid] = m;
        }
        #pragma unroll 2
        for (int it = 0; it < 18; it++) {
            int key4 = (w + it*8)*4;
            const unsigned* vp = kvbase + (long)key4*512 + 256 + h*32 + lane;
            uint4 pk;
            pk.x = vp[0]; pk.y = vp[512]; pk.z = vp[1024]; pk.w = vp[1536];
            *(uint4*)&Kt[lane*KT_STR + key4] = pk;
        }
        __syncthreads();                        // S3
        // ---- P4: e = exp(s - rowmax); Ss <- tf32(e); dual sums ----
        {
            float rm0 = rowmax[r4], rm1 = rowmax[r4+8];
            float psA[2] = {0.f,0.f};
            float psB[2] = {0.f,0.f};
            float* row0 = &Ss[r4*SSTR + w*72 + c4*2];
            float* row1 = row0 + 8*SSTR;
            #pragma unroll
            for (int nt = 0; nt < 9; nt++) {
                float e0 = __expf(acc[nt][0] - rm0);
                float e1 = __expf(acc[nt][1] - rm0);
                float e2 = __expf(acc[nt][2] - rm1);
                float e3 = __expf(acc[nt][3] - rm1);
                acc[nt][0] = e0; acc[nt][1] = e1;
                acc[nt][2] = e2; acc[nt][3] = e3;
                psA[0] += e0 + e1;
                psA[1] += e2 + e3;
                float f0  = __uint_as_float(f2tf(e0));
                float f1  = __uint_as_float(f2tf(e1));
                float f2v = __uint_as_float(f2tf(e2));
                float f3  = __uint_as_float(f2tf(e3));
                psB[0] += f0 + f1;
                psB[1] += f2v + f3;
                *(float2*)&row0[nt*8] = make_float2(f0, f1);
                *(float2*)&row1[nt*8] = make_float2(f2v, f3);
            }
            #pragma unroll
            for (int s = 0; s < 2; s++) {
                psA[s] += __shfl_xor_sync(0xffffffffu, psA[s], 1);
                psA[s] += __shfl_xor_sync(0xffffffffu, psA[s], 2);
                psB[s] += __shfl_xor_sync(0xffffffffu, psB[s], 1);
                psB[s] += __shfl_xor_sync(0xffffffffu, psB[s], 2);
            }
            if (c4 == 0) {
                pbufA[r4*8 + w]     = psA[0];
                pbufA[(r4+8)*8 + w] = psA[1];
                pbufB[r4*8 + w]     = psB[0];
                pbufB[(r4+8)*8 + w] = psB[1];
            }
        }
        __syncthreads();                        // S4
        if (tid < 16) {
            float sa = 0.f, sb = 0.f;
            #pragma unroll
            for (int i = 0; i < 8; i++) { sa += pbufA[tid*8 + i]; sb += pbufB[tid*8 + i]; }
            rinv0[tid] = __frcp_rn(sa);
            rinv1[tid] = __frcp_rn(sb);
        }
        __syncthreads();                        // S5
        // ---- P5: Am += exact e * rinv0 / 8 (registers) ----
        {
            float ra0 = rinv0[r4]*0.125f, ra1 = rinv0[r4+8]*0.125f;
            #pragma unroll
            for (int nt = 0; nt < 9; nt++) {
                am[nt][0] += acc[nt][0] * ra0;
                am[nt][1] += acc[nt][1] * ra0;
                am[nt][2] += acc[nt][2] * ra1;
                am[nt][3] += acc[nt][3] * ra1;
            }
        }
        // ---- P6: O = (E V) * rinv1; keys split across warp pairs; write split o2 ----
        {
            const int nt6 = w & 3, half = w >> 2;
            float dv[4] = {0.f, 0.f, 0.f, 0.f};
            const unsigned* Es  = (const unsigned*)Ss;
            const unsigned* e0b = &Es[r4*SSTR + half*288 + c4];
            const unsigned* e1b = e0b + 8*SSTR;
            const unsigned* vb  = &Kt[(nt6*8 + r4)*KT_STR + half*288 + c4];
            #pragma unroll 6
            for (int kc = 0; kc < 36; kc++) {
                unsigned a[4];
                a[0] = e0b[kc*8]; a[1] = e1b[kc*8];
                a[2] = e0b[kc*8 + 4]; a[3] = e1b[kc*8 + 4];
                mma_tf32(dv, a, vb[kc*8], vb[kc*8 + 4]);
            }
            __syncthreads();                    // S6a
            if (half == 1)
                *(float4*)&Ss[(nt6*32 + lane)*4] = make_float4(dv[0], dv[1], dv[2], dv[3]);
            __syncthreads();                    // S6b
            if (half == 0) {
                float4 p = *(float4*)&Ss[(nt6*32 + lane)*4];
                dv[0] += p.x; dv[1] += p.y; dv[2] += p.z; dv[3] += p.w;
                float ri0 = rinv1[r4], ri1 = rinv1[r4+8];
                float x0 = dv[0]*ri0, x1 = dv[1]*ri0;
                float x2 = dv[2]*ri1, x3 = dv[3]*ri1;
                long ob = qrow*512 + (h*32 + nt6*8 + c4*2)*2;
                unsigned h0=f2tf(x0), h1=f2tf(x1), h2=f2tf(x2), h3=f2tf(x3);
                *(uint4*)&g_o2[ob] =
                    make_uint4(h0, f2tf(x0-__uint_as_float(h0)), h1, f2tf(x1-__uint_as_float(h1)));
                *(uint4*)&g_o2[ob + 8*512] =
                    make_uint4(h2, f2tf(x2-__uint_as_float(h2)), h3, f2tf(x3-__uint_as_float(h3)));
            }
        }
    }
    // ---- final: head-mean attention from registers ----
    float* aout = attn_out + (long)(layer*NB + nb)*SEQ*SEQ + (long)qt*16*SEQ;
    #pragma unroll
    for (int nt = 0; nt < 9; nt++) {
        int col = w*72 + nt*8 + c4*2;
        *(float2*)&aout[(long)r4*SEQ + col]     = make_float2(am[nt][0], am[nt][1]);
        *(float2*)&aout[(long)(r4+8)*SEQ + col] = make_float2(am[nt][2], am[nt][3]);
    }
}

// ---------------- feature mean over sequence ----------------
__global__ void feat_k(void) {
    int ni = blockIdx.x, b = blockIdx.y, d = threadIdx.x;
    const float* p = g_pe + ((long)(ni*BATCH + b)*SEQ)*DIM + d;
    float s = 0.f;
    for (int t = 0; t < SEQ; t++) s += p[(long)t*DIM];
    g_feat[b*(NIMG*DIM) + ni*DIM + d] = s * (1.0f/576.0f);
}

// ---------------- MLP head ----------------
__global__ void head_k(const float* __restrict__ w1, const float* __restrict__ b1,
                       const float* __restrict__ w2, const float* __restrict__ b2,
                       float* __restrict__ out) {
    __shared__ float fs[NIMG*DIM];
    __shared__ float hs[MLPDIM];
    int b = blockIdx.x, tid = threadIdx.x;
    for (int t = tid; t < NIMG*DIM; t += MLPDIM) fs[t] = g_feat[b*NIMG*DIM + t];
    __syncthreads();
    float a = b1[tid];
    const float* wr = w1 + (long)tid*(NIMG*DIM);
    for (int d2 = 0; d2 < NIMG*DIM; d2++) a += fs[d2]*wr[d2];
    hs[tid] = fmaxf(a, 0.f) * w2[tid];
    __syncthreads();
    for (int st = 256; st > 0; st >>= 1) {
        if (tid < st) hs[tid] += hs[tid + st];
        __syncthreads();
    }
    if (tid == 0) out[b] = hs[0] + b2[0];
}

// ---------------- launch ----------------
extern "C" void kernel_launch(void* const* d_in, const int* in_sizes, int n_in,
                              void* d_out, int out_size) {
    const float* x      = (const float*)d_in[0];
    const float* conv_w = (const float*)d_in[1];
    const float* conv_b = (const float*)d_in[2];
    const float* pos_e  = (const float*)d_in[3];
    const float* in_w   = (const float*)d_in[4];
    const float* in_b   = (const float*)d_in[5];
    const float* out_w  = (const float*)d_in[6];
    const float* out_b  = (const float*)d_in[7];
    const float* hw1    = (const float*)d_in[8];
    const float* hb1    = (const float*)d_in[9];
    const float* hw2    = (const float*)d_in[10];
    const float* hb2    = (const float*)d_in[11];

    float* out  = (float*)d_out;            // [8]
    float* attn = out + BATCH;              // [6,4,8,576,576]

    cudaFuncSetAttribute(attn_mma, cudaFuncAttributeMaxDynamicSharedMemorySize, ATTN_SMEM);

    unsigned *im2_p, *pe2_p, *q2_p, *o2_p, *kvt_p, *cw2_p, *iw2_p, *ow2_p;
    float *pe_p;
    cudaGetSymbolAddress((void**)&im2_p, g_im2);
    cudaGetSymbolAddress((void**)&pe2_p, g_pe2);
    cudaGetSymbolAddress((void**)&q2_p,  g_q2);
    cudaGetSymbolAddress((void**)&o2_p,  g_o2);
    cudaGetSymbolAddress((void**)&kvt_p, g_kvt);
    cudaGetSymbolAddress((void**)&cw2_p, g_cw2);
    cudaGetSymbolAddress((void**)&iw2_p, g_iw2);
    cudaGetSymbolAddress((void**)&ow2_p, g_ow2);
    cudaGetSymbolAddress((void**)&pe_p,  g_pe);

    // 0) weight splits
    cvt_k<<<(NIMG*DIM*KPATCH + 255)/256, 256>>>(conv_w, cw2_p, NIMG*DIM*KPATCH);
    cvt_k<<<(NLAYER*3*DIM*DIM + 255)/256, 256>>>(in_w, iw2_p, NLAYER*3*DIM*DIM);
    cvt_k<<<(NLAYER*DIM*DIM + 255)/256, 256>>>(out_w, ow2_p, NLAYER*DIM*DIM);

    // 1) im2col (split)
    {
        long total = (long)NIMG*BATCH*SEQ*KPATCH;
        im2col_k<<<(int)((total + 255)/256), 256>>>(x);
    }
    // 2) patch-embed GEMM per image (+conv_b +pos) -> pe2
    {
        dim3 g(DIM/64, (BATCH*SEQ)/64, NIMG);
        gemm3x<<<g, 256>>>(im2_p, cw2_p, nullptr, pe2_p, nullptr,
                           BATCH*SEQ, DIM, KPATCH,
                           conv_b, pos_e,
                           (long)BATCH*SEQ*KPATCH*2, (long)DIM*KPATCH*2,
                           (long)BATCH*SEQ*DIM, DIM, 0);
    }
    // 3) transformer layers
    for (int l = 0; l < NLAYER; l++) {
        {   // qkv: pe2 -> q2 (scaled split) + kvt (tf32)
            dim3 g((3*DIM)/64, TOK/64, 1);
            gemm3x<<<g, 256>>>(pe2_p, iw2_p + (long)l*3*DIM*DIM*2,
                               nullptr, q2_p, kvt_p,
                               TOK, 3*DIM, DIM,
                               in_b + (long)l*3*DIM, nullptr, 0, 0, 0, 0, 1);
        }
        {
            dim3 g(SEQ/16, NB, 1);
            attn_mma<<<g, 256, ATTN_SMEM>>>(attn, l);
        }
        {   // out-proj: o2 -> pe f32 + pe2
            dim3 g(DIM/64, TOK/64, 1);
            gemm3x<<<g, 256>>>(o2_p, ow2_p + (long)l*DIM*DIM*2,
                               pe_p, pe2_p, nullptr,
                               TOK, DIM, DIM,
                               out_b + (long)l*DIM, nullptr, 0, 0, 0, 0, 0);
        }
    }
    // 4) sequence-mean features + MLP head
    {
        dim3 g(NIMG, BATCH);
        feat_k<<<g, DIM>>>();
    }
    head_k<<<BATCH, MLPDIM>>>(hw1, hb1, hw2, hb2, out);
}

// round 6
// speedup vs baseline: 1.2961x; 1.2961x over previous
#include <cuda_runtime.h>
#include <math.h>

// ---------------- problem constants ----------------
#define NIMG 4
#define BATCH 8
#define SEQ 576
#define DIM 256
#define NHEAD 8
#define DHEAD 32
#define NLAYER 6
#define MLPDIM 512
#define NB (NIMG*BATCH)      // 32
#define TOK (NB*SEQ)         // 18432
#define KPATCH 768           // 3*16*16
#define GRID24 24

// ---------------- scratch (device globals; no allocation allowed) ----------------
__device__ float g_im2col[(long)NIMG*BATCH*SEQ*KPATCH];  // 56.6 MB
__device__ float g_pe[(long)TOK*DIM];                    // 18.9 MB
__device__ float g_qkv[(long)TOK*3*DIM];                 // 56.6 MB
__device__ float g_o[(long)TOK*DIM];                     // 18.9 MB
__device__ float g_feat[BATCH*NIMG*DIM];

// ---------------- tf32 helpers ----------------
__device__ __forceinline__ unsigned f2tf(float f) {
    unsigned u; asm("cvt.rna.tf32.f32 %0, %1;" : "=r"(u) : "f"(f)); return u;
}
__device__ __forceinline__ void mma_tf32(float* d, const unsigned* a, unsigned b0, unsigned b1) {
    asm volatile(
        "mma.sync.aligned.m16n8k8.row.col.f32.tf32.tf32.f32 "
        "{%0,%1,%2,%3},{%4,%5,%6,%7},{%8,%9},{%0,%1,%2,%3};"
        : "+f"(d[0]), "+f"(d[1]), "+f"(d[2]), "+f"(d[3])
        : "r"(a[0]), "r"(a[1]), "r"(a[2]), "r"(a[3]), "r"(b0), "r"(b1));
}

// ---------------- im2col ----------------
__global__ void im2col_k(const float* __restrict__ x) {
    long idx = (long)blockIdx.x*256 + threadIdx.x;
    const long total = (long)NIMG*BATCH*SEQ*KPATCH;
    if (idx >= total) return;
    int k   = (int)(idx % KPATCH);
    long r  = idx / KPATCH;
    int s   = (int)(r % SEQ);
    int b   = (int)((r / SEQ) % BATCH);
    int ni  = (int)(r / ((long)SEQ*BATCH));
    int c   = k >> 8;
    int py  = (k >> 4) & 15;
    int px  = k & 15;
    int gy  = s / GRID24, gx = s % GRID24;
    g_im2col[idx] = x[(((long)b*12 + ni*3 + c)*384 + gy*16 + py)*384 + gx*16 + px];
}

// ---------------- scalar SGEMM (exact fp32, FFMA-roofline): C = A @ Bw^T ----------------
__global__ __launch_bounds__(256) void sgemm64(
    const float* __restrict__ A, const float* __restrict__ Bw, float* __restrict__ C,
    int M, int N, int K,
    const float* __restrict__ bias, const float* __restrict__ pos,
    long strideA, long strideB, long strideC, int strideBias)
{
    A  += (long)blockIdx.z * strideA;
    Bw += (long)blockIdx.z * strideB;
    C  += (long)blockIdx.z * strideC;
    if (bias) bias += (long)blockIdx.z * strideBias;

    __shared__ float As[16][68];
    __shared__ float Bs[16][68];

    int tid  = threadIdx.x;
    int m0   = blockIdx.y * 64;
    int n0   = blockIdx.x * 64;
    int arow = tid >> 2;
    int ac4  = (tid & 3) * 4;
    int tm   = tid >> 4;
    int tn   = tid & 15;

    float acc[4][4] = {};

    for (int k0 = 0; k0 < K; k0 += 16) {
        float4 av = *(const float4*)&A[(long)(m0 + arow)*K + k0 + ac4];
        float4 bv = *(const float4*)&Bw[(long)(n0 + arow)*K + k0 + ac4];
        As[ac4+0][arow] = av.x; As[ac4+1][arow] = av.y;
        As[ac4+2][arow] = av.z; As[ac4+3][arow] = av.w;
        Bs[ac4+0][arow] = bv.x; Bs[ac4+1][arow] = bv.y;
        Bs[ac4+2][arow] = bv.z; Bs[ac4+3][arow] = bv.w;
        __syncthreads();
        #pragma unroll
        for (int kk = 0; kk < 16; kk++) {
            float4 a = *(const float4*)&As[kk][tm*4];
            float4 b = *(const float4*)&Bs[kk][tn*4];
            acc[0][0] += a.x*b.x; acc[0][1] += a.x*b.y; acc[0][2] += a.x*b.z; acc[0][3] += a.x*b.w;
            acc[1][0] += a.y*b.x; acc[1][1] += a.y*b.y; acc[1][2] += a.y*b.z; acc[1][3] += a.y*b.w;
            acc[2][0] += a.z*b.x; acc[2][1] += a.z*b.y; acc[2][2] += a.z*b.z; acc[2][3] += a.z*b.w;
            acc[3][0] += a.w*b.x; acc[3][1] += a.w*b.y; acc[3][2] += a.w*b.z; acc[3][3] += a.w*b.w;
        }
        __syncthreads();
    }

    int n = n0 + tn*4;
    float4 bb = {0.f,0.f,0.f,0.f};
    if (bias) { bb.x = bias[n]; bb.y = bias[n+1]; bb.z = bias[n+2]; bb.w = bias[n+3]; }
    #pragma unroll
    for (int ii = 0; ii < 4; ii++) {
        int m = m0 + tm*4 + ii;
        float4 v;
        v.x = acc[ii][0] + bb.x; v.y = acc[ii][1] + bb.y;
        v.z = acc[ii][2] + bb.z; v.w = acc[ii][3] + bb.w;
        if (pos) {
            const float* pr = pos + (long)(m % SEQ)*DIM + n;
            v.x += pr[0]; v.y += pr[1]; v.z += pr[2]; v.w += pr[3];
        }
        *(float4*)&C[(long)m*N + n] = v;
    }
}

// ---------------- fused attention: 32-q tile, 512 threads, K+V both resident ----------------
#define KSTRD 580
#define SSTRD 580
// floats: Kt 18560 + Vt 18560 + Ss 18560 + pbufA 256 + pbufB 256 + rowmax 32 + rinv0 32 + rinv1 32
#define ATTN_FLOATS (3*32*580 + 256 + 256 + 96)
#define ATTN_SMEM (ATTN_FLOATS*4)   // 225,152 B

__global__ __launch_bounds__(512, 1) void attn_mma(
    const float* __restrict__ qkv, float* __restrict__ o,
    float* __restrict__ attn_out, int layer)
{
    extern __shared__ float sm[];
    unsigned* Kt   = (unsigned*)sm;             // [32 dh][580 key] tf32 K^T
    unsigned* Vt   = (unsigned*)(sm + 32*KSTRD);// [32 dh][580 key] tf32 V^T
    float* Ss      = sm + 2*32*KSTRD;           // [32 q][580 key] E; head: P6 scratch
    float* pbufA   = Ss + 32*SSTRD;             // [32][8]
    float* pbufB   = pbufA + 256;               // [32][8]
    float* rowmax  = pbufB + 256;               // [32]
    float* rinv0   = rowmax + 32;               // [32] 1/sum(exact e)
    float* rinv1   = rinv0 + 32;                // [32] 1/sum(tf32 e)

    const int tid  = threadIdx.x;
    const int lane = tid & 31;
    const int w    = tid >> 5;                  // 0..15
    const int r4   = lane >> 2;
    const int c4   = lane & 3;
    const int ws   = w >> 3;                    // q-subtile (16 q)
    const int wk   = w & 7;                     // key-slice (72 keys)
    const int qt   = blockIdx.x;                // 0..17
    const int nb   = blockIdx.y;                // 0..31
    const float* qbase = qkv + (long)nb*SEQ*768;
    const float SC = 0.17677669529663687f;      // 1/sqrt(32)

    float am[9][4];
    #pragma unroll
    for (int nt = 0; nt < 9; nt++)
        #pragma unroll
        for (int i = 0; i < 4; i++) am[nt][i] = 0.f;

    for (int h = 0; h < NHEAD; h++) {
        // ---- P1: load K^T and V^T [32 dh][576 key] as tf32 (16 warps) ----
        #pragma unroll 3
        for (int it = 0; it < 9; it++) {
            int key4 = (w + it*16)*4;
            const float* kp = qbase + (long)key4*768 + 256 + h*32 + lane;
            uint4 pk;
            pk.x = f2tf(kp[0]);
            pk.y = f2tf(kp[768]);
            pk.z = f2tf(kp[2*768]);
            pk.w = f2tf(kp[3*768]);
            *(uint4*)&Kt[lane*KSTRD + key4] = pk;
            const float* vp = kp + 256;
            uint4 pv;
            pv.x = f2tf(vp[0]);
            pv.y = f2tf(vp[768]);
            pv.z = f2tf(vp[2*768]);
            pv.w = f2tf(vp[3*768]);
            *(uint4*)&Vt[lane*KSTRD + key4] = pv;
        }
        __syncthreads();                        // S1

        // ---- P2: S = Q K^T, Q hi/lo split; warp (ws,wk) -> 16q x 72k ----
        float acc[9][4];
        #pragma unroll
        for (int nt = 0; nt < 9; nt++)
            #pragma unroll
            for (int i = 0; i < 4; i++) acc[nt][i] = 0.f;

        #pragma unroll
        for (int kc = 0; kc < 4; kc++) {
            unsigned ah[4], al[4];
            {
                const float* qp = qbase + (long)(qt*32 + ws*16 + r4)*768 + h*32 + kc*8 + c4;
                float q0 = qp[0]*SC, q1 = qp[8*768]*SC, q2 = qp[4]*SC, q3 = qp[8*768+4]*SC;
                ah[0]=f2tf(q0); al[0]=f2tf(q0-__uint_as_float(ah[0]));
                ah[1]=f2tf(q1); al[1]=f2tf(q1-__uint_as_float(ah[1]));
                ah[2]=f2tf(q2); al[2]=f2tf(q2-__uint_as_float(ah[2]));
                ah[3]=f2tf(q3); al[3]=f2tf(q3-__uint_as_float(ah[3]));
            }
            const unsigned* kb  = &Kt[(kc*8 + c4)*KSTRD + wk*72 + r4];
            const unsigned* kb4 = kb + 4*KSTRD;
            #pragma unroll
            for (int nt = 0; nt < 9; nt++) {
                unsigned b0 = kb[nt*8], b1 = kb4[nt*8];
                mma_tf32(acc[nt], ah, b0, b1);
                mma_tf32(acc[nt], al, b0, b1);
            }
        }
        // partial row max
        {
            float pm[2] = {-1e30f, -1e30f};
            #pragma unroll
            for (int nt = 0; nt < 9; nt++) {
                pm[0] = fmaxf(pm[0], fmaxf(acc[nt][0], acc[nt][1]));
                pm[1] = fmaxf(pm[1], fmaxf(acc[nt][2], acc[nt][3]));
            }
            #pragma unroll
            for (int s = 0; s < 2; s++) {
                pm[s] = fmaxf(pm[s], __shfl_xor_sync(0xffffffffu, pm[s], 1));
                pm[s] = fmaxf(pm[s], __shfl_xor_sync(0xffffffffu, pm[s], 2));
            }
            if (c4 == 0) {
                pbufA[(ws*16 + r4)*8 + wk]     = pm[0];
                pbufA[(ws*16 + 8 + r4)*8 + wk] = pm[1];
            }
        }
        __syncthreads();                        // S2
        if (tid < 32) {
            float m = pbufA[tid*8];
            #pragma unroll
            for (int i = 1; i < 8; i++) m = fmaxf(m, pbufA[tid*8 + i]);
            rowmax[tid] = m;
        }
        __syncthreads();                        // S3
        // ---- P4: e = exp(s - rowmax); Ss <- tf32(e); dual sums ----
        {
            float rm0 = rowmax[ws*16 + r4], rm1 = rowmax[ws*16 + 8 + r4];
            float psA[2] = {0.f,0.f};
            float psB[2] = {0.f,0.f};
            float* row0 = &Ss[(ws*16 + r4)*SSTRD + wk*72 + c4*2];
            float* row1 = row0 + 8*SSTRD;
            #pragma unroll
            for (int nt = 0; nt < 9; nt++) {
                float e0 = __expf(acc[nt][0] - rm0);
                float e1 = __expf(acc[nt][1] - rm0);
                float e2 = __expf(acc[nt][2] - rm1);
                float e3 = __expf(acc[nt][3] - rm1);
                acc[nt][0] = e0; acc[nt][1] = e1;
                acc[nt][2] = e2; acc[nt][3] = e3;
                psA[0] += e0 + e1;
                psA[1] += e2 + e3;
                float f0  = __uint_as_float(f2tf(e0));
                float f1  = __uint_as_float(f2tf(e1));
                float f2v = __uint_as_float(f2tf(e2));
                float f3  = __uint_as_float(f2tf(e3));
                psB[0] += f0 + f1;
                psB[1] += f2v + f3;
                *(float2*)&row0[nt*8] = make_float2(f0, f1);
                *(float2*)&row1[nt*8] = make_float2(f2v, f3);
            }
            #pragma unroll
            for (int s = 0; s < 2; s++) {
                psA[s] += __shfl_xor_sync(0xffffffffu, psA[s], 1);
                psA[s] += __shfl_xor_sync(0xffffffffu, psA[s], 2);
                psB[s] += __shfl_xor_sync(0xffffffffu, psB[s], 1);
                psB[s] += __shfl_xor_sync(0xffffffffu, psB[s], 2);
            }
            if (c4 == 0) {
                pbufA[(ws*16 + r4)*8 + wk]     = psA[0];
                pbufA[(ws*16 + 8 + r4)*8 + wk] = psA[1];
                pbufB[(ws*16 + r4)*8 + wk]     = psB[0];
                pbufB[(ws*16 + 8 + r4)*8 + wk] = psB[1];
            }
        }
        __syncthreads();                        // S4
        if (tid < 32) {
            float sa = 0.f, sb = 0.f;
            #pragma unroll
            for (int i = 0; i < 8; i++) { sa += pbufA[tid*8 + i]; sb += pbufB[tid*8 + i]; }
            rinv0[tid] = __frcp_rn(sa);
            rinv1[tid] = __frcp_rn(sb);
        }
        __syncthreads();                        // S5
        // ---- P5: Am += exact e * rinv0 / 8 (registers) ----
        {
            float ra0 = rinv0[ws*16 + r4]*0.125f, ra1 = rinv0[ws*16 + 8 + r4]*0.125f;
            #pragma unroll
            for (int nt = 0; nt < 9; nt++) {
                am[nt][0] += acc[nt][0] * ra0;
                am[nt][1] += acc[nt][1] * ra0;
                am[nt][2] += acc[nt][2] * ra1;
                am[nt][3] += acc[nt][3] * ra1;
            }
        }
        // ---- P6: O = (E V) * rinv1; warp=(mt,half,nt6); keys split in halves ----
        {
            const int nt6 = w & 3, half = (w >> 2) & 1, mt = w >> 3;
            float dv[4] = {0.f, 0.f, 0.f, 0.f};
            const unsigned* Es  = (const unsigned*)Ss;
            const unsigned* e0b = &Es[(mt*16 + r4)*SSTRD + half*288 + c4];
            const unsigned* e1b = e0b + 8*SSTRD;
            const unsigned* vb  = &Vt[(nt6*8 + r4)*KSTRD + half*288 + c4];
            #pragma unroll 6
            for (int kc = 0; kc < 36; kc++) {
                unsigned a[4];
                a[0] = e0b[kc*8]; a[1] = e1b[kc*8];
                a[2] = e0b[kc*8 + 4]; a[3] = e1b[kc*8 + 4];
                mma_tf32(dv, a, vb[kc*8], vb[kc*8 + 4]);
            }
            __syncthreads();                    // S6a: all E/V smem reads done
            if (half == 1)
                *(float4*)&Ss[((mt*4 + nt6)*32 + lane)*4] = make_float4(dv[0], dv[1], dv[2], dv[3]);
            __syncthreads();                    // S6b
            if (half == 0) {
                float4 p = *(float4*)&Ss[((mt*4 + nt6)*32 + lane)*4];
                dv[0] += p.x; dv[1] += p.y; dv[2] += p.z; dv[3] += p.w;
                float ri0 = rinv1[mt*16 + r4], ri1 = rinv1[mt*16 + 8 + r4];
                long orow = (long)(nb*SEQ + qt*32 + mt*16 + r4)*DIM + h*32 + nt6*8 + c4*2;
                *(float2*)&o[orow]         = make_float2(dv[0]*ri0, dv[1]*ri0);
                *(float2*)&o[orow + 8*DIM] = make_float2(dv[2]*ri1, dv[3]*ri1);
            }
        }
        // NOTE: next head's P1 only writes Kt/Vt (not the Ss scratch); the
        // lagging half==0 reads of Ss scratch are ordered before any P4 write
        // of the next iteration by the S1..S3 barriers. No extra barrier needed.
    }
    // ---- final: head-mean attention from registers ----
    float* aout = attn_out + (long)(layer*NB + nb)*SEQ*SEQ + (long)qt*32*SEQ;
    #pragma unroll
    for (int nt = 0; nt < 9; nt++) {
        int col = wk*72 + nt*8 + c4*2;
        *(float2*)&aout[(long)(ws*16 + r4)*SEQ + col]     = make_float2(am[nt][0], am[nt][1]);
        *(float2*)&aout[(long)(ws*16 + 8 + r4)*SEQ + col] = make_float2(am[nt][2], am[nt][3]);
    }
}

// ---------------- feature mean over sequence ----------------
__global__ void feat_k(void) {
    int ni = blockIdx.x, b = blockIdx.y, d = threadIdx.x;
    const float* p = g_pe + ((long)(ni*BATCH + b)*SEQ)*DIM + d;
    float s = 0.f;
    for (int t = 0; t < SEQ; t++) s += p[(long)t*DIM];
    g_feat[b*(NIMG*DIM) + ni*DIM + d] = s * (1.0f/576.0f);
}

// ---------------- MLP head ----------------
__global__ void head_k(const float* __restrict__ w1, const float* __restrict__ b1,
                       const float* __restrict__ w2, const float* __restrict__ b2,
                       float* __restrict__ out) {
    __shared__ float fs[NIMG*DIM];
    __shared__ float hs[MLPDIM];
    int b = blockIdx.x, tid = threadIdx.x;
    for (int t = tid; t < NIMG*DIM; t += MLPDIM) fs[t] = g_feat[b*NIMG*DIM + t];
    __syncthreads();
    float a = b1[tid];
    const float* wr = w1 + (long)tid*(NIMG*DIM);
    for (int d2 = 0; d2 < NIMG*DIM; d2++) a += fs[d2]*wr[d2];
    hs[tid] = fmaxf(a, 0.f) * w2[tid];
    __syncthreads();
    for (int st = 256; st > 0; st >>= 1) {
        if (tid < st) hs[tid] += hs[tid + st];
        __syncthreads();
    }
    if (tid == 0) out[b] = hs[0] + b2[0];
}

// ---------------- launch ----------------
extern "C" void kernel_launch(void* const* d_in, const int* in_sizes, int n_in,
                              void* d_out, int out_size) {
    const float* x      = (const float*)d_in[0];
    const float* conv_w = (const float*)d_in[1];
    const float* conv_b = (const float*)d_in[2];
    const float* pos_e  = (const float*)d_in[3];
    const float* in_w   = (const float*)d_in[4];
    const float* in_b   = (const float*)d_in[5];
    const float* out_w  = (const float*)d_in[6];
    const float* out_b  = (const float*)d_in[7];
    const float* hw1    = (const float*)d_in[8];
    const float* hb1    = (const float*)d_in[9];
    const float* hw2    = (const float*)d_in[10];
    const float* hb2    = (const float*)d_in[11];

    float* out  = (float*)d_out;            // [8]
    float* attn = out + BATCH;              // [6,4,8,576,576]

    cudaFuncSetAttribute(attn_mma, cudaFuncAttributeMaxDynamicSharedMemorySize, ATTN_SMEM);

    float *im2col_p, *pe_p, *qkv_p, *o_p;
    cudaGetSymbolAddress((void**)&im2col_p, g_im2col);
    cudaGetSymbolAddress((void**)&pe_p,     g_pe);
    cudaGetSymbolAddress((void**)&qkv_p,    g_qkv);
    cudaGetSymbolAddress((void**)&o_p,      g_o);

    // 1) im2col
    {
        long total = (long)NIMG*BATCH*SEQ*KPATCH;
        im2col_k<<<(int)((total + 255)/256), 256>>>(x);
    }
    // 2) patch-embed GEMM per image, + conv_b + pos_enc
    {
        dim3 g(DIM/64, (BATCH*SEQ)/64, NIMG);
        sgemm64<<<g, 256>>>(im2col_p, conv_w, pe_p,
                            BATCH*SEQ, DIM, KPATCH,
                            conv_b, pos_e,
                            (long)BATCH*SEQ*KPATCH, (long)DIM*KPATCH,
                            (long)BATCH*SEQ*DIM, DIM);
    }
    // 3) transformer layers
    for (int l = 0; l < NLAYER; l++) {
        {
            dim3 g((3*DIM)/64, TOK/64, 1);
            sgemm64<<<g, 256>>>(pe_p, in_w + (long)l*3*DIM*DIM, qkv_p,
                                TOK, 3*DIM, DIM,
                                in_b + (long)l*3*DIM, nullptr, 0, 0, 0, 0);
        }
        {
            dim3 g(SEQ/32, NB, 1);
            attn_mma<<<g, 512, ATTN_SMEM>>>(qkv_p, o_p, attn, l);
        }
        {
            dim3 g(DIM/64, TOK/64, 1);
            sgemm64<<<g, 256>>>(o_p, out_w + (long)l*DIM*DIM, pe_p,
                                TOK, DIM, DIM,
                                out_b + (long)l*DIM, nullptr, 0, 0, 0, 0);
        }
    }
    // 4) sequence-mean features + MLP head
    {
        dim3 g(NIMG, BATCH);
        feat_k<<<g, DIM>>>();
    }
    head_k<<<BATCH, MLPDIM>>>(hw1, hb1, hw2, hb2, out);
}

// round 8
// speedup vs baseline: 1.5899x; 1.2267x over previous
#include <cuda_runtime.h>
#include <cuda_bf16.h>
#include <math.h>

// ---------------- problem constants ----------------
#define NIMG 4
#define BATCH 8
#define SEQ 576
#define DIM 256
#define NHEAD 8
#define DHEAD 32
#define NLAYER 6
#define MLPDIM 512
#define NB (NIMG*BATCH)      // 32
#define TOK (NB*SEQ)         // 18432
#define KPATCH 768           // 3*16*16
#define GRID24 24

// ---------------- scratch (device globals; no allocation allowed) ----------------
// bf16 hi/lo planes (hi+lo = 4B/elem, same traffic as f32)
__device__ __nv_bfloat16 g_imh[(long)NIMG*BATCH*SEQ*KPATCH];
__device__ __nv_bfloat16 g_iml[(long)NIMG*BATCH*SEQ*KPATCH];
__device__ __nv_bfloat16 g_peh[(long)TOK*DIM];
__device__ __nv_bfloat16 g_pel[(long)TOK*DIM];
__device__ __nv_bfloat16 g_oh [(long)TOK*DIM];
__device__ __nv_bfloat16 g_ol [(long)TOK*DIM];
__device__ __nv_bfloat16 g_cwh[(long)NIMG*DIM*KPATCH];
__device__ __nv_bfloat16 g_cwl[(long)NIMG*DIM*KPATCH];
__device__ __nv_bfloat16 g_iwh[(long)NLAYER*3*DIM*DIM];
__device__ __nv_bfloat16 g_iwl[(long)NLAYER*3*DIM*DIM];
__device__ __nv_bfloat16 g_owh[(long)NLAYER*DIM*DIM];
__device__ __nv_bfloat16 g_owl[(long)NLAYER*DIM*DIM];
__device__ float g_qkv[(long)TOK*3*DIM];                 // 56.6 MB
__device__ float g_pe [(long)TOK*DIM];                   // 18.9 MB (f32 for feat)
__device__ float g_feat[BATCH*NIMG*DIM];

// ---------------- helpers ----------------
__device__ __forceinline__ unsigned f2tf(float f) {
    unsigned u; asm("cvt.rna.tf32.f32 %0, %1;" : "=r"(u) : "f"(f)); return u;
}
__device__ __forceinline__ void mma_tf32(float* d, const unsigned* a, unsigned b0, unsigned b1) {
    asm volatile(
        "mma.sync.aligned.m16n8k8.row.col.f32.tf32.tf32.f32 "
        "{%0,%1,%2,%3},{%4,%5,%6,%7},{%8,%9},{%0,%1,%2,%3};"
        : "+f"(d[0]), "+f"(d[1]), "+f"(d[2]), "+f"(d[3])
        : "r"(a[0]), "r"(a[1]), "r"(a[2]), "r"(a[3]), "r"(b0), "r"(b1));
}
__device__ __forceinline__ void mma_bf16(float* d, const unsigned* a, unsigned b0, unsigned b1) {
    asm volatile(
        "mma.sync.aligned.m16n8k16.row.col.f32.bf16.bf16.f32 "
        "{%0,%1,%2,%3},{%4,%5,%6,%7},{%8,%9},{%0,%1,%2,%3};"
        : "+f"(d[0]), "+f"(d[1]), "+f"(d[2]), "+f"(d[3])
        : "r"(a[0]), "r"(a[1]), "r"(a[2]), "r"(a[3]), "r"(b0), "r"(b1));
}
__device__ __forceinline__ void splitbf(float v, __nv_bfloat16& h, __nv_bfloat16& l) {
    h = __float2bfloat16(v);
    l = __float2bfloat16(v - __bfloat162float(h));
}

// ---------------- weight split kernel ----------------
__global__ void cvt_bf(const float* __restrict__ s,
                       __nv_bfloat16* __restrict__ h, __nv_bfloat16* __restrict__ l, int n) {
    int i = blockIdx.x*256 + threadIdx.x;
    if (i >= n) return;
    splitbf(s[i], h[i], l[i]);
}

// ---------------- im2col (split bf16 planes) ----------------
__global__ void im2col_k(const float* __restrict__ x) {
    long idx = (long)blockIdx.x*256 + threadIdx.x;
    const long total = (long)NIMG*BATCH*SEQ*KPATCH;
    if (idx >= total) return;
    int k   = (int)(idx % KPATCH);
    long r  = idx / KPATCH;
    int s   = (int)(r % SEQ);
    int b   = (int)((r / SEQ) % BATCH);
    int ni  = (int)(r / ((long)SEQ*BATCH));
    int c   = k >> 8;
    int py  = (k >> 4) & 15;
    int px  = k & 15;
    int gy  = s / GRID24, gx = s % GRID24;
    float v = x[(((long)b*12 + ni*3 + c)*384 + gy*16 + py)*384 + gx*16 + px];
    splitbf(v, g_imh[idx], g_iml[idx]);
}

// ---------------- bf16x3 tensor GEMM: C[M,N] = A[M,K] @ Bw[N,K]^T ----------------
// A/B given as separate bf16 hi/lo planes. D = Ah*Bh + Al*Bh + Ah*Bl (f32 accum).
// 64x64 CTA tile, k-tile 32, 256 threads (8 warps, each 16x32 output).
#define BSTR 40
__global__ __launch_bounds__(256) void gemm_bf3(
    const __nv_bfloat16* __restrict__ Ah, const __nv_bfloat16* __restrict__ Al,
    const __nv_bfloat16* __restrict__ Bh, const __nv_bfloat16* __restrict__ Bl,
    float* __restrict__ Cf, __nv_bfloat16* __restrict__ Ch, __nv_bfloat16* __restrict__ Cl,
    int M, int N, int K,
    const float* __restrict__ bias, const float* __restrict__ pos,
    long strideA, long strideB, long strideC, int strideBias)
{
    Ah += (long)blockIdx.z * strideA;  Al += (long)blockIdx.z * strideA;
    Bh += (long)blockIdx.z * strideB;  Bl += (long)blockIdx.z * strideB;
    if (Cf) Cf += (long)blockIdx.z * strideC;
    if (Ch) { Ch += (long)blockIdx.z * strideC; Cl += (long)blockIdx.z * strideC; }
    if (bias) bias += (long)blockIdx.z * strideBias;

    __shared__ __nv_bfloat16 sAh[64][BSTR], sAl[64][BSTR];
    __shared__ __nv_bfloat16 sBh[64][BSTR], sBl[64][BSTR];

    const int tid  = threadIdx.x;
    const int lane = tid & 31;
    const int w    = tid >> 5;
    const int r4   = lane >> 2;
    const int c4   = lane & 3;
    const int wm   = w & 3, wn = w >> 2;
    const int m0   = blockIdx.y * 64, n0 = blockIdx.x * 64;
    const int lrow = tid >> 2;
    const int lk8  = (tid & 3) * 8;

    float acc[4][4] = {};

    for (int k0 = 0; k0 < K; k0 += 32) {
        long ga = (long)(m0 + lrow)*K + k0 + lk8;
        long gb = (long)(n0 + lrow)*K + k0 + lk8;
        *(uint4*)&sAh[lrow][lk8] = *(const uint4*)&Ah[ga];
        *(uint4*)&sAl[lrow][lk8] = *(const uint4*)&Al[ga];
        *(uint4*)&sBh[lrow][lk8] = *(const uint4*)&Bh[gb];
        *(uint4*)&sBl[lrow][lk8] = *(const uint4*)&Bl[gb];
        __syncthreads();
        #pragma unroll
        for (int kk = 0; kk < 2; kk++) {
            int kb = kk*16 + c4*2;
            int ar0 = wm*16 + r4, ar1 = ar0 + 8;
            unsigned ah[4], al[4];
            ah[0] = *(const unsigned*)&sAh[ar0][kb];
            ah[1] = *(const unsigned*)&sAh[ar1][kb];
            ah[2] = *(const unsigned*)&sAh[ar0][kb+8];
            ah[3] = *(const unsigned*)&sAh[ar1][kb+8];
            al[0] = *(const unsigned*)&sAl[ar0][kb];
            al[1] = *(const unsigned*)&sAl[ar1][kb];
            al[2] = *(const unsigned*)&sAl[ar0][kb+8];
            al[3] = *(const unsigned*)&sAl[ar1][kb+8];
            #pragma unroll
            for (int nt = 0; nt < 4; nt++) {
                int bc = wn*32 + nt*8 + r4;
                unsigned bh0 = *(const unsigned*)&sBh[bc][kb];
                unsigned bh1 = *(const unsigned*)&sBh[bc][kb+8];
                unsigned bl0 = *(const unsigned*)&sBl[bc][kb];
                unsigned bl1 = *(const unsigned*)&sBl[bc][kb+8];
                mma_bf16(acc[nt], ah, bh0, bh1);
                mma_bf16(acc[nt], al, bh0, bh1);
                mma_bf16(acc[nt], ah, bl0, bl1);
            }
        }
        __syncthreads();
    }

    #pragma unroll
    for (int nt = 0; nt < 4; nt++) {
        int n = n0 + wn*32 + nt*8 + c4*2;
        float bx = 0.f, by = 0.f;
        if (bias) { bx = bias[n]; by = bias[n+1]; }
        int row0 = m0 + wm*16 + r4, row1 = row0 + 8;
        float v00 = acc[nt][0]+bx, v01 = acc[nt][1]+by;
        float v10 = acc[nt][2]+bx, v11 = acc[nt][3]+by;
        if (pos) {
            const float* p0 = pos + (long)(row0 % SEQ)*DIM + n;
            const float* p1 = pos + (long)(row1 % SEQ)*DIM + n;
            v00 += p0[0]; v01 += p0[1]; v10 += p1[0]; v11 += p1[1];
        }
        if (Cf) {
            *(float2*)&Cf[(long)row0*N + n] = make_float2(v00, v01);
            *(float2*)&Cf[(long)row1*N + n] = make_float2(v10, v11);
        }
        if (Ch) {
            __nv_bfloat162 h0, l0, h1, l1;
            splitbf(v00, h0.x, l0.x); splitbf(v01, h0.y, l0.y);
            splitbf(v10, h1.x, l1.x); splitbf(v11, h1.y, l1.y);
            *(__nv_bfloat162*)&Ch[(long)row0*N + n] = h0;
            *(__nv_bfloat162*)&Cl[(long)row0*N + n] = l0;
            *(__nv_bfloat162*)&Ch[(long)row1*N + n] = h1;
            *(__nv_bfloat162*)&Cl[(long)row1*N + n] = l1;
        }
    }
}

// ---------------- fused attention: 32-q tile, 512 threads, K+V both resident ----------------
#define KSTRD 580
#define SSTRD 580
#define ATTN_FLOATS (3*32*580 + 256 + 256 + 96)
#define ATTN_SMEM (ATTN_FLOATS*4)   // 225,152 B

__global__ __launch_bounds__(512, 1) void attn_mma(
    const float* __restrict__ qkv, float* __restrict__ attn_out, int layer)
{
    extern __shared__ float sm[];
    unsigned* Kt   = (unsigned*)sm;             // [32 dh][580 key] tf32 K^T
    unsigned* Vt   = (unsigned*)(sm + 32*KSTRD);// [32 dh][580 key] tf32 V^T
    float* Ss      = sm + 2*32*KSTRD;           // [32 q][580 key] E; P6 scratch at head
    float* pbufA   = Ss + 32*SSTRD;             // [32][8]
    float* pbufB   = pbufA + 256;               // [32][8]
    float* rowmax  = pbufB + 256;               // [32]
    float* rinv0   = rowmax + 32;               // [32] 1/sum(exact e)
    float* rinv1   = rinv0 + 32;                // [32] 1/sum(tf32 e)

    const int tid  = threadIdx.x;
    const int lane = tid & 31;
    const int w    = tid >> 5;                  // 0..15
    const int r4   = lane >> 2;
    const int c4   = lane & 3;
    const int ws   = w >> 3;                    // q-subtile (16 q)
    const int wk   = w & 7;                     // key-slice (72 keys)
    const int qt   = blockIdx.x;                // 0..17
    const int nb   = blockIdx.y;                // 0..31
    const float* qbase = qkv + (long)nb*SEQ*768;
    const float SC = 0.17677669529663687f;      // 1/sqrt(32)

    float am[9][4];
    #pragma unroll
    for (int nt = 0; nt < 9; nt++)
        #pragma unroll
        for (int i = 0; i < 4; i++) am[nt][i] = 0.f;

    for (int h = 0; h < NHEAD; h++) {
        // ---- P1: load K^T and V^T as tf32 ----
        #pragma unroll 3
        for (int it = 0; it < 9; it++) {
            int key4 = (w + it*16)*4;
            const float* kp = qbase + (long)key4*768 + 256 + h*32 + lane;
            uint4 pk;
            pk.x = f2tf(kp[0]);
            pk.y = f2tf(kp[768]);
            pk.z = f2tf(kp[2*768]);
            pk.w = f2tf(kp[3*768]);
            *(uint4*)&Kt[lane*KSTRD + key4] = pk;
            const float* vp = kp + 256;
            uint4 pv;
            pv.x = f2tf(vp[0]);
            pv.y = f2tf(vp[768]);
            pv.z = f2tf(vp[2*768]);
            pv.w = f2tf(vp[3*768]);
            *(uint4*)&Vt[lane*KSTRD + key4] = pv;
        }
        __syncthreads();                        // S1

        // ---- P2: S = Q K^T, Q hi/lo split; warp (ws,wk) -> 16q x 72k ----
        float acc[9][4];
        #pragma unroll
        for (int nt = 0; nt < 9; nt++)
            #pragma unroll
            for (int i = 0; i < 4; i++) acc[nt][i] = 0.f;

        #pragma unroll
        for (int kc = 0; kc < 4; kc++) {
            unsigned ah[4], al[4];
            {
                const float* qp = qbase + (long)(qt*32 + ws*16 + r4)*768 + h*32 + kc*8 + c4;
                float q0 = qp[0]*SC, q1 = qp[8*768]*SC, q2 = qp[4]*SC, q3 = qp[8*768+4]*SC;
                ah[0]=f2tf(q0); al[0]=f2tf(q0-__uint_as_float(ah[0]));
                ah[1]=f2tf(q1); al[1]=f2tf(q1-__uint_as_float(ah[1]));
                ah[2]=f2tf(q2); al[2]=f2tf(q2-__uint_as_float(ah[2]));
                ah[3]=f2tf(q3); al[3]=f2tf(q3-__uint_as_float(ah[3]));
            }
            const unsigned* kb  = &Kt[(kc*8 + c4)*KSTRD + wk*72 + r4];
            const unsigned* kb4 = kb + 4*KSTRD;
            #pragma unroll
            for (int nt = 0; nt < 9; nt++) {
                unsigned b0 = kb[nt*8], b1 = kb4[nt*8];
                mma_tf32(acc[nt], ah, b0, b1);
                mma_tf32(acc[nt], al, b0, b1);
            }
        }
        // partial row max
        {
            float pm[2] = {-1e30f, -1e30f};
            #pragma unroll
            for (int nt = 0; nt < 9; nt++) {
                pm[0] = fmaxf(pm[0], fmaxf(acc[nt][0], acc[nt][1]));
                pm[1] = fmaxf(pm[1], fmaxf(acc[nt][2], acc[nt][3]));
            }
            #pragma unroll
            for (int s = 0; s < 2; s++) {
                pm[s] = fmaxf(pm[s], __shfl_xor_sync(0xffffffffu, pm[s], 1));
                pm[s] = fmaxf(pm[s], __shfl_xor_sync(0xffffffffu, pm[s], 2));
            }
            if (c4 == 0) {
                pbufA[(ws*16 + r4)*8 + wk]     = pm[0];
                pbufA[(ws*16 + 8 + r4)*8 + wk] = pm[1];
            }
        }
        __syncthreads();                        // S2
        if (tid < 32) {
            float m = pbufA[tid*8];
            #pragma unroll
            for (int i = 1; i < 8; i++) m = fmaxf(m, pbufA[tid*8 + i]);
            rowmax[tid] = m;
        }
        __syncthreads();                        // S3
        // ---- P4: e = exp(s - rowmax); Ss <- tf32(e); dual sums ----
        {
            float rm0 = rowmax[ws*16 + r4], rm1 = rowmax[ws*16 + 8 + r4];
            float psA[2] = {0.f,0.f};
            float psB[2] = {0.f,0.f};
            float* row0 = &Ss[(ws*16 + r4)*SSTRD + wk*72 + c4*2];
            float* row1 = row0 + 8*SSTRD;
            #pragma unroll
            for (int nt = 0; nt < 9; nt++) {
                float e0 = __expf(acc[nt][0] - rm0);
                float e1 = __expf(acc[nt][1] - rm0);
                float e2 = __expf(acc[nt][2] - rm1);
                float e3 = __expf(acc[nt][3] - rm1);
                acc[nt][0] = e0; acc[nt][1] = e1;
                acc[nt][2] = e2; acc[nt][3] = e3;
                psA[0] += e0 + e1;
                psA[1] += e2 + e3;
                float f0  = __uint_as_float(f2tf(e0));
                float f1  = __uint_as_float(f2tf(e1));
                float f2v = __uint_as_float(f2tf(e2));
                float f3  = __uint_as_float(f2tf(e3));
                psB[0] += f0 + f1;
                psB[1] += f2v + f3;
                *(float2*)&row0[nt*8] = make_float2(f0, f1);
                *(float2*)&row1[nt*8] = make_float2(f2v, f3);
            }
            #pragma unroll
            for (int s = 0; s < 2; s++) {
                psA[s] += __shfl_xor_sync(0xffffffffu, psA[s], 1);
                psA[s] += __shfl_xor_sync(0xffffffffu, psA[s], 2);
                psB[s] += __shfl_xor_sync(0xffffffffu, psB[s], 1);
                psB[s] += __shfl_xor_sync(0xffffffffu, psB[s], 2);
            }
            if (c4 == 0) {
                pbufA[(ws*16 + r4)*8 + wk]     = psA[0];
                pbufA[(ws*16 + 8 + r4)*8 + wk] = psA[1];
                pbufB[(ws*16 + r4)*8 + wk]     = psB[0];
                pbufB[(ws*16 + 8 + r4)*8 + wk] = psB[1];
            }
        }
        __syncthreads();                        // S4
        if (tid < 32) {
            float sa = 0.f, sb = 0.f;
            #pragma unroll
            for (int i = 0; i < 8; i++) { sa += pbufA[tid*8 + i]; sb += pbufB[tid*8 + i]; }
            rinv0[tid] = __frcp_rn(sa);
            rinv1[tid] = __frcp_rn(sb);
        }
        __syncthreads();                        // S5
        // ---- P5: Am += exact e * rinv0 / 8 (registers) ----
        {
            float ra0 = rinv0[ws*16 + r4]*0.125f, ra1 = rinv0[ws*16 + 8 + r4]*0.125f;
            #pragma unroll
            for (int nt = 0; nt < 9; nt++) {
                am[nt][0] += acc[nt][0] * ra0;
                am[nt][1] += acc[nt][1] * ra0;
                am[nt][2] += acc[nt][2] * ra1;
                am[nt][3] += acc[nt][3] * ra1;
            }
        }
        // ---- P6: O = (E V) * rinv1; write split bf16 planes ----
        {
            const int nt6 = w & 3, half = (w >> 2) & 1, mt = w >> 3;
            float dv[4] = {0.f, 0.f, 0.f, 0.f};
            const unsigned* Es  = (const unsigned*)Ss;
            const unsigned* e0b = &Es[(mt*16 + r4)*SSTRD + half*288 + c4];
            const unsigned* e1b = e0b + 8*SSTRD;
            const unsigned* vb  = &Vt[(nt6*8 + r4)*KSTRD + half*288 + c4];
            #pragma unroll 6
            for (int kc = 0; kc < 36; kc++) {
                unsigned a[4];
                a[0] = e0b[kc*8]; a[1] = e1b[kc*8];
                a[2] = e0b[kc*8 + 4]; a[3] = e1b[kc*8 + 4];
                mma_tf32(dv, a, vb[kc*8], vb[kc*8 + 4]);
            }
            __syncthreads();                    // S6a
            if (half == 1)
                *(float4*)&Ss[((mt*4 + nt6)*32 + lane)*4] = make_float4(dv[0], dv[1], dv[2], dv[3]);
            __syncthreads();                    // S6b
            if (half == 0) {
                float4 p = *(float4*)&Ss[((mt*4 + nt6)*32 + lane)*4];
                dv[0] += p.x; dv[1] += p.y; dv[2] += p.z; dv[3] += p.w;
                float ri0 = rinv1[mt*16 + r4], ri1 = rinv1[mt*16 + 8 + r4];
                float x0 = dv[0]*ri0, x1 = dv[1]*ri0;
                float x2 = dv[2]*ri1, x3 = dv[3]*ri1;
                long orow = (long)(nb*SEQ + qt*32 + mt*16 + r4)*DIM + h*32 + nt6*8 + c4*2;
                __nv_bfloat162 h0, l0, h1, l1;
                splitbf(x0, h0.x, l0.x); splitbf(x1, h0.y, l0.y);
                splitbf(x2, h1.x, l1.x); splitbf(x3, h1.y, l1.y);
                *(__nv_bfloat162*)&g_oh[orow]         = h0;
                *(__nv_bfloat162*)&g_ol[orow]         = l0;
                *(__nv_bfloat162*)&g_oh[orow + 8*DIM] = h1;
                *(__nv_bfloat162*)&g_ol[orow + 8*DIM] = l1;
            }
        }
    }
    // ---- final: head-mean attention from registers ----
    float* aout = attn_out + (long)(layer*NB + nb)*SEQ*SEQ + (long)qt*32*SEQ;
    #pragma unroll
    for (int nt = 0; nt < 9; nt++) {
        int col = wk*72 + nt*8 + c4*2;
        *(float2*)&aout[(long)(ws*16 + r4)*SEQ + col]     = make_float2(am[nt][0], am[nt][1]);
        *(float2*)&aout[(long)(ws*16 + 8 + r4)*SEQ + col] = make_float2(am[nt][2], am[nt][3]);
    }
}

// ---------------- feature mean over sequence ----------------
__global__ void feat_k(void) {
    int ni = blockIdx.x, b = blockIdx.y, d = threadIdx.x;
    const float* p = g_pe + ((long)(ni*BATCH + b)*SEQ)*DIM + d;
    float s = 0.f;
    for (int t = 0; t < SEQ; t++) s += p[(long)t*DIM];
    g_feat[b*(NIMG*DIM) + ni*DIM + d] = s * (1.0f/576.0f);
}

// ---------------- MLP head ----------------
__global__ void head_k(const float* __restrict__ w1, const float* __restrict__ b1,
                       const float* __restrict__ w2, const float* __restrict__ b2,
                       float* __restrict__ out) {
    __shared__ float fs[NIMG*DIM];
    __shared__ float hs[MLPDIM];
    int b = blockIdx.x, tid = threadIdx.x;
    for (int t = tid; t < NIMG*DIM; t += MLPDIM) fs[t] = g_feat[b*NIMG*DIM + t];
    __syncthreads();
    float a = b1[tid];
    const float* wr = w1 + (long)tid*(NIMG*DIM);
    for (int d2 = 0; d2 < NIMG*DIM; d2++) a += fs[d2]*wr[d2];
    hs[tid] = fmaxf(a, 0.f) * w2[tid];
    __syncthreads();
    for (int st = 256; st > 0; st >>= 1) {
        if (tid < st) hs[tid] += hs[tid + st];
        __syncthreads();
    }
    if (tid == 0) out[b] = hs[0] + b2[0];
}

// ---------------- launch ----------------
extern "C" void kernel_launch(void* const* d_in, const int* in_sizes, int n_in,
                              void* d_out, int out_size) {
    const float* x      = (const float*)d_in[0];
    const float* conv_w = (const float*)d_in[1];
    const float* conv_b = (const float*)d_in[2];
    const float* pos_e  = (const float*)d_in[3];
    const float* in_w   = (const float*)d_in[4];
    const float* in_b   = (const float*)d_in[5];
    const float* out_w  = (const float*)d_in[6];
    const float* out_b  = (const float*)d_in[7];
    const float* hw1    = (const float*)d_in[8];
    const float* hb1    = (const float*)d_in[9];
    const float* hw2    = (const float*)d_in[10];
    const float* hb2    = (const float*)d_in[11];

    float* out  = (float*)d_out;            // [8]
    float* attn = out + BATCH;              // [6,4,8,576,576]

    cudaFuncSetAttribute(attn_mma, cudaFuncAttributeMaxDynamicSharedMemorySize, ATTN_SMEM);

    __nv_bfloat16 *imh_p, *iml_p, *peh_p, *pel_p, *oh_p, *ol_p;
    __nv_bfloat16 *cwh_p, *cwl_p, *iwh_p, *iwl_p, *owh_p, *owl_p;
    float *qkv_p, *pe_p;
    cudaGetSymbolAddress((void**)&imh_p, g_imh);
    cudaGetSymbolAddress((void**)&iml_p, g_iml);
    cudaGetSymbolAddress((void**)&peh_p, g_peh);
    cudaGetSymbolAddress((void**)&pel_p, g_pel);
    cudaGetSymbolAddress((void**)&oh_p,  g_oh);
    cudaGetSymbolAddress((void**)&ol_p,  g_ol);
    cudaGetSymbolAddress((void**)&cwh_p, g_cwh);
    cudaGetSymbolAddress((void**)&cwl_p, g_cwl);
    cudaGetSymbolAddress((void**)&iwh_p, g_iwh);
    cudaGetSymbolAddress((void**)&iwl_p, g_iwl);
    cudaGetSymbolAddress((void**)&owh_p, g_owh);
    cudaGetSymbolAddress((void**)&owl_p, g_owl);
    cudaGetSymbolAddress((void**)&qkv_p, g_qkv);
    cudaGetSymbolAddress((void**)&pe_p,  g_pe);

    // 0) weight splits
    cvt_bf<<<(NIMG*DIM*KPATCH + 255)/256, 256>>>(conv_w, cwh_p, cwl_p, NIMG*DIM*KPATCH);
    cvt_bf<<<(NLAYER*3*DIM*DIM + 255)/256, 256>>>(in_w, iwh_p, iwl_p, NLAYER*3*DIM*DIM);
    cvt_bf<<<(NLAYER*DIM*DIM + 255)/256, 256>>>(out_w, owh_p, owl_p, NLAYER*DIM*DIM);

    // 1) im2col (split)
    {
        long total = (long)NIMG*BATCH*SEQ*KPATCH;
        im2col_k<<<(int)((total + 255)/256), 256>>>(x);
    }
    // 2) patch-embed GEMM per image (+conv_b +pos) -> peh/pel
    {
        dim3 g(DIM/64, (BATCH*SEQ)/64, NIMG);
        gemm_bf3<<<g, 256>>>(imh_p, iml_p, cwh_p, cwl_p,
                             nullptr, peh_p, pel_p,
                             BATCH*SEQ, DIM, KPATCH,
                             conv_b, pos_e,
                             (long)BATCH*SEQ*KPATCH, (long)DIM*KPATCH,
                             (long)BATCH*SEQ*DIM, DIM);
    }
    // 3) transformer layers
    for (int l = 0; l < NLAYER; l++) {
        {   // qkv: (peh,pel) x in_w -> f32 qkv
            dim3 g((3*DIM)/64, TOK/64, 1);
            gemm_bf3<<<g, 256>>>(peh_p, pel_p,
                                 iwh_p + (long)l*3*DIM*DIM, iwl_p + (long)l*3*DIM*DIM,
                                 qkv_p, nullptr, nullptr,
                                 TOK, 3*DIM, DIM,
                                 in_b + (long)l*3*DIM, nullptr, 0, 0, 0, 0);
        }
        {
            dim3 g(SEQ/32, NB, 1);
            attn_mma<<<g, 512, ATTN_SMEM>>>(qkv_p, attn, l);
        }
        {   // out-proj: (oh,ol) x out_w -> pe f32 + peh/pel
            dim3 g(DIM/64, TOK/64, 1);
            gemm_bf3<<<g, 256>>>(oh_p, ol_p,
                                 owh_p + (long)l*DIM*DIM, owl_p + (long)l*DIM*DIM,
                                 pe_p, peh_p, pel_p,
                                 TOK, DIM, DIM,
                                 out_b + (long)l*DIM, nullptr, 0, 0, 0, 0);
        }
    }
    // 4) sequence-mean features + MLP head
    {
        dim3 g(NIMG, BATCH);
        feat_k<<<g, DIM>>>();
    }
    head_k<<<BATCH, MLPDIM>>>(hw1, hb1, hw2, hb2, out);
}